// round 9
// baseline (speedup 1.0000x reference)
#include <cuda_runtime.h>
#include <cuda_bf16.h>
#include <cuda_fp16.h>
#include <math.h>
#include <stdint.h>

#define S_LEN 4096
#define HID 4096
#define NH 32
#define NKV 8
#define DH 128
#define ATT_SCALE 0.08838834764831845f  // 1/sqrt(128)

// ---------------- scratch ----------------
__device__ float g_Q[S_LEN * NH * DH];
__device__ float g_K[S_LEN * NKV * DH];
__device__ float g_V[S_LEN * NKV * DH];
__device__ float g_attn[S_LEN * NH * DH];
__device__ __nv_bfloat16 g_hsHi[S_LEN * HID];
__device__ __nv_bfloat16 g_hsLo[S_LEN * HID];
__device__ __half g_hs16h[S_LEN * HID];
__device__ __half g_hs16l[S_LEN * HID];
__device__ __nv_bfloat16 g_wqTHi[HID * HID];
__device__ __nv_bfloat16 g_wqTLo[HID * HID];
__device__ __nv_bfloat16 g_wkTHi[(NKV * DH) * HID];
__device__ __nv_bfloat16 g_wkTLo[(NKV * DH) * HID];
__device__ __half g_wvT16[(NKV * DH) * HID];
__device__ __half g_woT16[HID * HID];
__device__ __half g_at16h[S_LEN * NH * DH];
__device__ __half g_at16l[S_LEN * NH * DH];

// ================= helpers =================
__device__ __forceinline__ uint32_t smem_u32(const void* p) {
    uint32_t a;
    asm("{ .reg .u64 t; cvta.to.shared.u64 t, %1; cvt.u32.u64 %0, t; }" : "=r"(a) : "l"(p));
    return a;
}
__device__ __forceinline__ uint32_t swz(uint32_t o) { return o ^ ((o >> 3) & 0x70); }
// packed row-pair layout for 64B rows (verified in R7)
__device__ __forceinline__ uint32_t pk(uint32_t r, uint32_t cb) {
    return ((r >> 1) << 7) + ((r & 1) << 6) + cb;
}

__device__ __forceinline__ void ldsm_x4(uint32_t& r0, uint32_t& r1, uint32_t& r2, uint32_t& r3,
                                        uint32_t addr) {
    asm volatile("ldmatrix.sync.aligned.m8n8.x4.shared.b16 {%0, %1, %2, %3}, [%4];"
                 : "=r"(r0), "=r"(r1), "=r"(r2), "=r"(r3) : "r"(addr));
}

template <typename T> struct MmaOp;
template <> struct MmaOp<__nv_bfloat16> {
    static __device__ __forceinline__ void run(float* c, const uint32_t* a, uint32_t b0,
                                               uint32_t b1) {
        asm volatile(
            "mma.sync.aligned.m16n8k16.row.col.f32.bf16.bf16.f32 "
            "{%0, %1, %2, %3}, {%4, %5, %6, %7}, {%8, %9}, {%0, %1, %2, %3};"
            : "+f"(c[0]), "+f"(c[1]), "+f"(c[2]), "+f"(c[3])
            : "r"(a[0]), "r"(a[1]), "r"(a[2]), "r"(a[3]), "r"(b0), "r"(b1));
    }
};
template <> struct MmaOp<__half> {
    static __device__ __forceinline__ void run(float* c, const uint32_t* a, uint32_t b0,
                                               uint32_t b1) {
        asm volatile(
            "mma.sync.aligned.m16n8k16.row.col.f32.f16.f16.f32 "
            "{%0, %1, %2, %3}, {%4, %5, %6, %7}, {%8, %9}, {%0, %1, %2, %3};"
            : "+f"(c[0]), "+f"(c[1]), "+f"(c[2]), "+f"(c[3])
            : "r"(a[0]), "r"(a[1]), "r"(a[2]), "r"(a[3]), "r"(b0), "r"(b1));
    }
};

__device__ __forceinline__ void cp16(uint32_t dst, const void* src) {
    asm volatile("cp.async.cg.shared.global [%0], [%1], 16;" :: "r"(dst), "l"(src));
}
#define CP_COMMIT() asm volatile("cp.async.commit_group;" ::: "memory")
#define CP_WAIT2() asm volatile("cp.async.wait_group 2;" ::: "memory")

// packed f32x2
typedef unsigned long long ull;
__device__ __forceinline__ ull fma2(ull a, ull b, ull c) {
    ull d;
    asm("fma.rn.f32x2 %0, %1, %2, %3;" : "=l"(d) : "l"(a), "l"(b), "l"(c));
    return d;
}
__device__ __forceinline__ ull dup2(float a) {
    ull d;
    asm("mov.b64 %0, {%1, %1};" : "=l"(d) : "f"(a));
    return d;
}
__device__ __forceinline__ float lo2(ull a) {
    float x, y;
    asm("mov.b64 {%0, %1}, %2;" : "=f"(x), "=f"(y) : "l"(a));
    return x + y;
}
__device__ __forceinline__ float2 unp2(ull a) {
    float2 r;
    asm("mov.b64 {%0, %1}, %2;" : "=f"(r.x), "=f"(r.y) : "l"(a));
    return r;
}

// ================= conversion kernels =================
__global__ void split_all_kernel(const float* __restrict__ in,
                                 __nv_bfloat16* __restrict__ hi,
                                 __nv_bfloat16* __restrict__ lo,
                                 __half* __restrict__ h16,
                                 __half* __restrict__ l16) {
    int i = (blockIdx.x * 256 + threadIdx.x) * 4;
    float4 v = *(const float4*)&in[i];
    float f[4] = {v.x, v.y, v.z, v.w};
    union { __nv_bfloat16 b[4]; uint2 u; } H, L;
    union { __half b[4]; uint2 u; } H16, L16;
#pragma unroll
    for (int j = 0; j < 4; ++j) {
        __nv_bfloat16 h = __float2bfloat16(f[j]);
        H.b[j] = h;
        L.b[j] = __float2bfloat16(f[j] - __bfloat162float(h));
        __half p = __float2half_rn(f[j]);
        H16.b[j] = p;
        L16.b[j] = __float2half_rn(f[j] - __half2float(p));
    }
    *(uint2*)&hi[i] = H.u;
    *(uint2*)&lo[i] = L.u;
    *(uint2*)&h16[i] = H16.u;
    *(uint2*)&l16[i] = L16.u;
}

__global__ void transpose_split_kernel(const float* __restrict__ W,
                                       __nv_bfloat16* __restrict__ hi,
                                       __nv_bfloat16* __restrict__ lo,
                                       int rows, int cols) {
    __shared__ float t[32][33];
    int c0 = blockIdx.x * 32, r0 = blockIdx.y * 32;
    int tx = threadIdx.x, ty = threadIdx.y;
#pragma unroll
    for (int j = 0; j < 4; ++j) {
        int r = ty + j * 8;
        t[r][tx] = W[(size_t)(r0 + r) * cols + c0 + tx];
    }
    __syncthreads();
#pragma unroll
    for (int j = 0; j < 4; ++j) {
        int r = ty + j * 8;
        float v = t[tx][r];
        __nv_bfloat16 h = __float2bfloat16(v);
        size_t o = (size_t)(c0 + r) * rows + r0 + tx;
        hi[o] = h;
        lo[o] = __float2bfloat16(v - __bfloat162float(h));
    }
}

__global__ void transpose_f16_kernel(const float* __restrict__ W,
                                     __half* __restrict__ out, int rows, int cols) {
    __shared__ float t[32][33];
    int c0 = blockIdx.x * 32, r0 = blockIdx.y * 32;
    int tx = threadIdx.x, ty = threadIdx.y;
#pragma unroll
    for (int j = 0; j < 4; ++j) {
        int r = ty + j * 8;
        t[r][tx] = W[(size_t)(r0 + r) * cols + c0 + tx];
    }
    __syncthreads();
#pragma unroll
    for (int j = 0; j < 4; ++j) {
        int r = ty + j * 8;
        out[(size_t)(c0 + r) * rows + r0 + tx] = __float2half_rn(t[tx][r]);
    }
}

// ================= HMMA GEMM: 4-stage, single barrier per chunk =================
// CTA 128x64, 256 thr (8 warps 4x2, warp tile 32x32), K-chunk 32, 2 CTAs/SM.
// Packed row-pair smem layout (32-elem rows = 64B, paired into 128B lines).
template <typename T, bool SPLIT_B>
__global__ __launch_bounds__(256, 2)
void gemm_tc(const T* __restrict__ Ahi, const T* __restrict__ Alo,
             const T* __restrict__ Bhi, const T* __restrict__ Blo,
             float* __restrict__ C, int N, int K) {
    constexpr uint32_t A_SZ = 8192;   // 128 rows x 64B
    constexpr uint32_t B_SZ = 4096;   // 64 rows x 64B
    constexpr uint32_t AB = 2 * A_SZ;
    constexpr uint32_t STG = AB + (SPLIT_B ? 2 * B_SZ : B_SZ);  // 24K / 20K
    extern __shared__ char smem[];
    const uint32_t sb = smem_u32(smem);
    const int tid = threadIdx.x, lane = tid & 31, wid = tid >> 5;
    const int m0 = blockIdx.y * 128, n0 = blockIdx.x * 64;
    const int wm = (wid >> 1) * 32, wn = (wid & 1) * 32;

    // A: 128 rows x 4 chunks = 512 / 256 thr = 2 each; B: 64 x 4 = 256 = 1 each
    const T* aptr[2];
    uint32_t asw[2];
#pragma unroll
    for (int i = 0; i < 2; ++i) {
        int idx = tid + (i << 8);
        int r = idx >> 2, c = idx & 3;
        aptr[i] = Ahi + (size_t)(m0 + r) * K + c * 8;
        asw[i] = swz(pk(r, c * 16));
    }
    const T* bptr = Bhi + (size_t)(n0 + (tid >> 2)) * K + (tid & 3) * 8;
    const uint32_t bsw = swz(pk(tid >> 2, (tid & 3) * 16));
    const ptrdiff_t dA = Alo - Ahi;
    const ptrdiff_t dB = SPLIT_B ? (Blo - Bhi) : 0;

    float acc[2][4][4];
#pragma unroll
    for (int mt = 0; mt < 2; ++mt)
#pragma unroll
        for (int nt = 0; nt < 4; ++nt)
#pragma unroll
            for (int q = 0; q < 4; ++q) acc[mt][nt][q] = 0.f;

    const int NKT = K >> 5;
    // prologue: stages 0..2
#pragma unroll
    for (int s = 0; s < 3; ++s) {
        const uint32_t st = sb + s * STG;
        const int ko = s * 32;
#pragma unroll
        for (int i = 0; i < 2; ++i) {
            cp16(st + asw[i], aptr[i] + ko);
            cp16(st + A_SZ + asw[i], aptr[i] + dA + ko);
        }
        cp16(st + AB + bsw, bptr + ko);
        if (SPLIT_B) cp16(st + AB + B_SZ + bsw, bptr + dB + ko);
        CP_COMMIT();
    }

    const int row_off = ((lane >> 3) & 1) * 8 + (lane & 7);
    const uint32_t lane_flat = ((uint32_t)(row_off >> 1) << 7) +
                               ((uint32_t)(row_off & 1) << 6) + ((lane >> 4) * 16);

    for (int kt = 0; kt < NKT; ++kt) {
        CP_WAIT2();
        __syncthreads();
        // prefetch stage kt+3 (single barrier: buffer (kt+3)&3 held stage kt-1,
        // which all warps finished before this barrier)
        if (kt + 3 < NKT) {
            const uint32_t st2 = sb + (uint32_t)((kt + 3) & 3) * STG;
            const int ko = (kt + 3) * 32;
#pragma unroll
            for (int i = 0; i < 2; ++i) {
                cp16(st2 + asw[i], aptr[i] + ko);
                cp16(st2 + A_SZ + asw[i], aptr[i] + dA + ko);
            }
            cp16(st2 + AB + bsw, bptr + ko);
            if (SPLIT_B) cp16(st2 + AB + B_SZ + bsw, bptr + dB + ko);
        }
        CP_COMMIT();

        const uint32_t st = sb + (uint32_t)(kt & 3) * STG;
#pragma unroll
        for (int ks = 0; ks < 2; ++ks) {
            const uint32_t kof = lane_flat + ks * 32;
            uint32_t ah[2][4], al[2][4], bh[2][4];
#pragma unroll
            for (int mt = 0; mt < 2; ++mt) {
                uint32_t off = swz(((uint32_t)(wm + mt * 16) << 6) + kof);
                ldsm_x4(ah[mt][0], ah[mt][1], ah[mt][2], ah[mt][3], st + off);
                ldsm_x4(al[mt][0], al[mt][1], al[mt][2], al[mt][3], st + A_SZ + off);
            }
#pragma unroll
            for (int nt2 = 0; nt2 < 2; ++nt2)
                ldsm_x4(bh[nt2][0], bh[nt2][1], bh[nt2][2], bh[nt2][3],
                        st + AB + swz(((uint32_t)(wn + nt2 * 16) << 6) + kof));
            if (SPLIT_B) {
                uint32_t bl[2][4];
#pragma unroll
                for (int nt2 = 0; nt2 < 2; ++nt2)
                    ldsm_x4(bl[nt2][0], bl[nt2][1], bl[nt2][2], bl[nt2][3],
                            st + AB + B_SZ + swz(((uint32_t)(wn + nt2 * 16) << 6) + kof));
#pragma unroll
                for (int mt = 0; mt < 2; ++mt)
#pragma unroll
                    for (int nt = 0; nt < 4; ++nt) {
                        MmaOp<T>::run(acc[mt][nt], ah[mt],
                                      bh[nt >> 1][nt & 1], bh[nt >> 1][2 + (nt & 1)]);
                        MmaOp<T>::run(acc[mt][nt], ah[mt],
                                      bl[nt >> 1][nt & 1], bl[nt >> 1][2 + (nt & 1)]);
                        MmaOp<T>::run(acc[mt][nt], al[mt],
                                      bh[nt >> 1][nt & 1], bh[nt >> 1][2 + (nt & 1)]);
                    }
            } else {
#pragma unroll
                for (int mt = 0; mt < 2; ++mt)
#pragma unroll
                    for (int nt = 0; nt < 4; ++nt) {
                        MmaOp<T>::run(acc[mt][nt], ah[mt],
                                      bh[nt >> 1][nt & 1], bh[nt >> 1][2 + (nt & 1)]);
                        MmaOp<T>::run(acc[mt][nt], al[mt],
                                      bh[nt >> 1][nt & 1], bh[nt >> 1][2 + (nt & 1)]);
                    }
            }
        }
    }

#pragma unroll
    for (int mt = 0; mt < 2; ++mt) {
        const int row = m0 + wm + mt * 16 + (lane >> 2);
#pragma unroll
        for (int nt = 0; nt < 4; ++nt) {
            const int col = n0 + wn + nt * 8 + (lane & 3) * 2;
            float* p0 = C + (size_t)row * N + col;
            *(float2*)p0 = make_float2(acc[mt][nt][0], acc[mt][nt][1]);
            *(float2*)(p0 + 8 * (size_t)N) = make_float2(acc[mt][nt][2], acc[mt][nt][3]);
        }
    }
}

// ---------------- RoPE ----------------
__global__ void rope_kernel(float* __restrict__ X, int nh) {
    const int s = blockIdx.x;
    const int d = threadIdx.x;
    const float e = (float)d * (1.0f / 64.0f);
    const float invf = 1.0f / powf(10000.0f, e);
    const float ang = (float)s * invf;
    float sn, cs;
    sincosf(ang, &sn, &cs);
    float* p = X + (size_t)s * nh * DH;
    for (int h = 0; h < nh; ++h) {
        const float x1 = p[d];
        const float x2 = p[d + 64];
        p[d] = x1 * cs - x2 * sn;
        p[d + 64] = x2 * cs + x1 * sn;
        p += DH;
    }
}

// ---------------- local windowed attention (512 threads, f32x2) ----------------
#define QP 132
#define KP 132
__global__ __launch_bounds__(512, 1)
void local_attn_kernel(const float* __restrict__ Q, const float* __restrict__ K,
                       const float* __restrict__ V, float* __restrict__ O) {
    extern __shared__ float sm[];
    float* sq = sm;
    float* sk = sq + 64 * QP;
    float* sv = sk + 128 * KP;
    float* sc = sv + 128 * 128;

    const int tid = threadIdx.x;
    const int h = blockIdx.y;
    const int n = blockIdx.x;
    const int kvh = h >> 2;
    const int q0 = n * 64;
    const int key0 = q0 - 64;

#pragma unroll
    for (int it = 0; it < 4; ++it) {
        int idx = tid + it * 512;
        int r = idx >> 5, c4 = idx & 31;
        float4 v4 = *(const float4*)&Q[(size_t)(q0 + r) * (NH * DH) + h * DH + c4 * 4];
        *(float4*)&sq[r * QP + c4 * 4] = v4;
    }
#pragma unroll
    for (int it = 0; it < 8; ++it) {
        int idx = tid + it * 512;
        int r = idx >> 5, c4 = idx & 31;
        int pos = key0 + r;
        float4 kv = make_float4(0.f, 0.f, 0.f, 0.f);
        float4 vv = make_float4(0.f, 0.f, 0.f, 0.f);
        if (pos >= 0) {
            kv = *(const float4*)&K[(size_t)pos * (NKV * DH) + kvh * DH + c4 * 4];
            vv = *(const float4*)&V[(size_t)pos * (NKV * DH) + kvh * DH + c4 * 4];
        }
        *(float4*)&sk[r * KP + c4 * 4] = kv;
        *(float4*)&sv[r * 128 + c4 * 4] = vv;
    }
    __syncthreads();

    // scores: 8 threads per query, 8 keys each (+1 extra for jo==0)
    {
        const int i = tid >> 3;
        const int jo = tid & 7;
        ull s2[8];
        ull s642 = 0;
#pragma unroll
        for (int m = 0; m < 8; ++m) s2[m] = 0;
        const float* qrow = sq + i * QP;
        for (int d0 = 0; d0 < 128; d0 += 8) {
            ull q2[4];
            q2[0] = *(const ull*)&qrow[d0];
            q2[1] = *(const ull*)&qrow[d0 + 2];
            q2[2] = *(const ull*)&qrow[d0 + 4];
            q2[3] = *(const ull*)&qrow[d0 + 6];
#pragma unroll
            for (int m = 0; m < 8; ++m) {
                const ull* kr = (const ull*)(sk + (i + jo + 8 * m) * KP + d0);
#pragma unroll
                for (int dd = 0; dd < 4; ++dd) s2[m] = fma2(q2[dd], kr[dd], s2[m]);
            }
            if (jo == 0) {
                const ull* kr = (const ull*)(sk + (i + 64) * KP + d0);
#pragma unroll
                for (int dd = 0; dd < 4; ++dd) s642 = fma2(q2[dd], kr[dd], s642);
            }
        }
#pragma unroll
        for (int m = 0; m < 8; ++m) sc[i * 66 + jo + 8 * m] = lo2(s2[m]) * ATT_SCALE;
        if (jo == 0) sc[i * 66 + 64] = lo2(s642) * ATT_SCALE;
    }
    __syncthreads();

    if (tid < 64) {
        float* row = sc + tid * 66;
        float mx = row[0];
        for (int j = 1; j < 65; ++j) mx = fmaxf(mx, row[j]);
        float sum = 0.f;
        for (int j = 0; j < 65; ++j) {
            float ex = expf(row[j] - mx);
            row[j] = ex;
            sum += ex;
        }
        float inv = 1.f / sum;
        for (int j = 0; j < 65; ++j) row[j] *= inv;
    }
    __syncthreads();

    // AV: 16 warps, 4 queries each
    {
        const int w = tid >> 5, lane = tid & 31;
        for (int iq = 0; iq < 4; ++iq) {
            const int i = w * 4 + iq;
            const float* wrow = sc + i * 66;
            ull o0 = 0, o1 = 0;
#pragma unroll 5
            for (int jj = 0; jj < 65; ++jj) {
                ull wt2 = dup2(wrow[jj]);
                const ull* v2 = (const ull*)(sv + (i + jj) * 128 + lane * 4);
                o0 = fma2(wt2, v2[0], o0);
                o1 = fma2(wt2, v2[1], o1);
            }
            float2 a = unp2(o0), b = unp2(o1);
            float4 res = make_float4(0.7f * a.x, 0.7f * a.y, 0.7f * b.x, 0.7f * b.y);
            *(float4*)&O[(size_t)(q0 + i) * (NH * DH) + h * DH + lane * 4] = res;
        }
    }
}

// ---------------- landmark attention (512 threads, f32x2; writes fp16 hi/lo) ----------------
__global__ __launch_bounds__(512, 1)
void lm_attn_kernel(const float* __restrict__ Q, const float* __restrict__ K,
                    const float* __restrict__ V, const float* __restrict__ OL,
                    __half* __restrict__ atHi, __half* __restrict__ atLo) {
    extern __shared__ float sm[];
    float* sq = sm;
    float* slk = sq + 64 * QP;
    float* slv = slk + 64 * QP;
    float* sc = slv + 64 * 128;

    const int tid = threadIdx.x;
    const int h = blockIdx.y;
    const int c = blockIdx.x;
    const int kvh = h >> 2;
    const int q0 = c * 64;
    const int nvis = c + 1;

#pragma unroll
    for (int it = 0; it < 4; ++it) {
        int idx = tid + it * 512;
        int r = idx >> 5, c4 = idx & 31;
        *(float4*)&sq[r * QP + c4 * 4] =
            *(const float4*)&Q[(size_t)(q0 + r) * (NH * DH) + h * DH + c4 * 4];
    }
#pragma unroll
    for (int it = 0; it < 4; ++it) {
        int idx = tid + it * 512;
        int r = idx >> 5, c4 = idx & 31;
        int pos = r * 64;
        *(float4*)&slk[r * QP + c4 * 4] =
            *(const float4*)&K[(size_t)pos * (NKV * DH) + kvh * DH + c4 * 4];
        *(float4*)&slv[r * 128 + c4 * 4] =
            *(const float4*)&V[(size_t)pos * (NKV * DH) + kvh * DH + c4 * 4];
    }
    __syncthreads();

    {
        const int i = tid >> 3;
        const int jo = tid & 7;
        ull s2[8];
#pragma unroll
        for (int m = 0; m < 8; ++m) s2[m] = 0;
        const float* qrow = sq + i * QP;
        for (int d0 = 0; d0 < 128; d0 += 8) {
            ull q2[4];
            q2[0] = *(const ull*)&qrow[d0];
            q2[1] = *(const ull*)&qrow[d0 + 2];
            q2[2] = *(const ull*)&qrow[d0 + 4];
            q2[3] = *(const ull*)&qrow[d0 + 6];
#pragma unroll
            for (int m = 0; m < 8; ++m) {
                const ull* kr = (const ull*)(slk + (jo + 8 * m) * QP + d0);
#pragma unroll
                for (int dd = 0; dd < 4; ++dd) s2[m] = fma2(q2[dd], kr[dd], s2[m]);
            }
        }
#pragma unroll
        for (int m = 0; m < 8; ++m) {
            int jj = jo + 8 * m;
            if (jj < nvis) sc[i * 66 + jj] = lo2(s2[m]) * ATT_SCALE;
        }
    }
    __syncthreads();

    if (tid < 64) {
        float* row = sc + tid * 66;
        float mx = row[0];
        for (int j = 1; j < nvis; ++j) mx = fmaxf(mx, row[j]);
        float sum = 0.f;
        for (int j = 0; j < nvis; ++j) {
            float ex = expf(row[j] - mx);
            row[j] = ex;
            sum += ex;
        }
        float inv = 1.f / sum;
        for (int j = 0; j < nvis; ++j) row[j] *= inv;
    }
    __syncthreads();

    {
        const int w = tid >> 5, lane = tid & 31;
        for (int iq = 0; iq < 4; ++iq) {
            const int i = w * 4 + iq;
            const float* wrow = sc + i * 66;
            ull o0 = 0, o1 = 0;
            for (int jj = 0; jj < nvis; ++jj) {
                ull wt2 = dup2(wrow[jj]);
                const ull* v2 = (const ull*)(slv + jj * 128 + lane * 4);
                o0 = fma2(wt2, v2[0], o0);
                o1 = fma2(wt2, v2[1], o1);
            }
            float2 a = unp2(o0), b = unp2(o1);
            size_t idx = (size_t)(q0 + i) * (NH * DH) + h * DH + lane * 4;
            float4 old = *(const float4*)&OL[idx];
            float s4[4] = {old.x + 0.3f * a.x, old.y + 0.3f * a.y,
                           old.z + 0.3f * b.x, old.w + 0.3f * b.y};
            union { __half b2[4]; uint2 u; } H, L;
#pragma unroll
            for (int q = 0; q < 4; ++q) {
                __half hb = __float2half_rn(s4[q]);
                H.b2[q] = hb;
                L.b2[q] = __float2half_rn(s4[q] - __half2float(hb));
            }
            *(uint2*)&atHi[idx] = H.u;
            *(uint2*)&atLo[idx] = L.u;
        }
    }
}

// ---------------- launch ----------------
extern "C" void kernel_launch(void* const* d_in, const int* in_sizes, int n_in,
                              void* d_out, int out_size) {
    const float* hs = (const float*)d_in[0];
    const float* wq = (const float*)d_in[1];
    const float* wk = (const float*)d_in[2];
    const float* wv = (const float*)d_in[3];
    const float* wo = (const float*)d_in[4];
    float* out = (float*)d_out;

    float *Q, *K, *V, *AT;
    __nv_bfloat16 *hsHi, *hsLo, *wqTHi, *wqTLo, *wkTHi, *wkTLo;
    __half *hs16h, *hs16l, *wvT16, *woT16, *at16h, *at16l;
    cudaGetSymbolAddress((void**)&Q, g_Q);
    cudaGetSymbolAddress((void**)&K, g_K);
    cudaGetSymbolAddress((void**)&V, g_V);
    cudaGetSymbolAddress((void**)&AT, g_attn);
    cudaGetSymbolAddress((void**)&hsHi, g_hsHi);
    cudaGetSymbolAddress((void**)&hsLo, g_hsLo);
    cudaGetSymbolAddress((void**)&hs16h, g_hs16h);
    cudaGetSymbolAddress((void**)&hs16l, g_hs16l);
    cudaGetSymbolAddress((void**)&wqTHi, g_wqTHi);
    cudaGetSymbolAddress((void**)&wqTLo, g_wqTLo);
    cudaGetSymbolAddress((void**)&wkTHi, g_wkTHi);
    cudaGetSymbolAddress((void**)&wkTLo, g_wkTLo);
    cudaGetSymbolAddress((void**)&wvT16, g_wvT16);
    cudaGetSymbolAddress((void**)&woT16, g_woT16);
    cudaGetSymbolAddress((void**)&at16h, g_at16h);
    cudaGetSymbolAddress((void**)&at16l, g_at16l);

    const int SMEM_LOCAL = (64 * QP + 128 * KP + 128 * 128 + 64 * 66) * 4;
    const int SMEM_LM = (64 * QP + 64 * QP + 64 * 128 + 64 * 66) * 4;
    const int SMEM_G3 = 4 * 24576;  // 98304
    const int SMEM_G2 = 4 * 20480;  // 81920
    cudaFuncSetAttribute(local_attn_kernel, cudaFuncAttributeMaxDynamicSharedMemorySize, SMEM_LOCAL);
    cudaFuncSetAttribute(lm_attn_kernel, cudaFuncAttributeMaxDynamicSharedMemorySize, SMEM_LM);
    cudaFuncSetAttribute(gemm_tc<__nv_bfloat16, true>,
                         cudaFuncAttributeMaxDynamicSharedMemorySize, SMEM_G3);
    cudaFuncSetAttribute(gemm_tc<__half, false>,
                         cudaFuncAttributeMaxDynamicSharedMemorySize, SMEM_G2);

    // 1-3: conversions feeding Q gemm
    split_all_kernel<<<(S_LEN * HID) / 1024, 256>>>(hs, hsHi, hsLo, hs16h, hs16l);
    transpose_split_kernel<<<dim3(HID / 32, HID / 32), dim3(32, 8)>>>(wq, wqTHi, wqTLo, HID, HID);
    transpose_f16_kernel<<<dim3((NKV * DH) / 32, HID / 32), dim3(32, 8)>>>(wv, wvT16, HID, NKV * DH);

    // 4: Q gemm (ncu capture slot)
    gemm_tc<__nv_bfloat16, true><<<dim3((NH * DH) / 64, S_LEN / 128), 256, SMEM_G3>>>(
        hsHi, hsLo, wqTHi, wqTLo, Q, NH * DH, HID);

    transpose_split_kernel<<<dim3((NKV * DH) / 32, HID / 32), dim3(32, 8)>>>(wk, wkTHi, wkTLo, HID, NKV * DH);
    gemm_tc<__nv_bfloat16, true><<<dim3((NKV * DH) / 64, S_LEN / 128), 256, SMEM_G3>>>(
        hsHi, hsLo, wkTHi, wkTLo, K, NKV * DH, HID);

    gemm_tc<__half, false><<<dim3((NKV * DH) / 64, S_LEN / 128), 256, SMEM_G2>>>(
        hs16h, hs16l, wvT16, (const __half*)nullptr, V, NKV * DH, HID);

    transpose_f16_kernel<<<dim3(HID / 32, HID / 32), dim3(32, 8)>>>(wo, woT16, HID, HID);

    rope_kernel<<<S_LEN, 64>>>(Q, NH);
    rope_kernel<<<S_LEN, 64>>>(K, NKV);

    local_attn_kernel<<<dim3(S_LEN / 64, NH), 512, SMEM_LOCAL>>>(Q, K, V, AT);
    lm_attn_kernel<<<dim3(S_LEN / 64, NH), 512, SMEM_LM>>>(Q, K, V, AT, at16h, at16l);

    gemm_tc<__half, false><<<dim3(HID / 64, S_LEN / 128), 256, SMEM_G2>>>(
        at16h, at16l, woT16, (const __half*)nullptr, out, HID, HID);
}

// round 10
// speedup vs baseline: 1.1035x; 1.1035x over previous
#include <cuda_runtime.h>
#include <cuda_bf16.h>
#include <cuda_fp16.h>
#include <math.h>
#include <stdint.h>

#define S_LEN 4096
#define HID 4096
#define NH 32
#define NKV 8
#define DH 128
#define ATT_SCALE 0.08838834764831845f  // 1/sqrt(128)

// ---------------- scratch ----------------
__device__ float g_Q[S_LEN * NH * DH];
__device__ float g_K[S_LEN * NKV * DH];
__device__ float g_V[S_LEN * NKV * DH];
__device__ float g_attn[S_LEN * NH * DH];
__device__ __nv_bfloat16 g_hsHi[S_LEN * HID];
__device__ __nv_bfloat16 g_hsLo[S_LEN * HID];
__device__ __half g_hs16h[S_LEN * HID];
__device__ __half g_hs16l[S_LEN * HID];
__device__ __nv_bfloat16 g_wqTHi[HID * HID];
__device__ __nv_bfloat16 g_wqTLo[HID * HID];
__device__ __nv_bfloat16 g_wkTHi[(NKV * DH) * HID];
__device__ __nv_bfloat16 g_wkTLo[(NKV * DH) * HID];
__device__ __half g_wvT16[(NKV * DH) * HID];
__device__ __half g_woT16[HID * HID];
__device__ __half g_at16h[S_LEN * NH * DH];
__device__ __half g_at16l[S_LEN * NH * DH];

// ================= helpers =================
__device__ __forceinline__ uint32_t smem_u32(const void* p) {
    uint32_t a;
    asm("{ .reg .u64 t; cvta.to.shared.u64 t, %1; cvt.u32.u64 %0, t; }" : "=r"(a) : "l"(p));
    return a;
}
__device__ __forceinline__ uint32_t swz(uint32_t o) { return o ^ ((o >> 3) & 0x70); }

__device__ __forceinline__ void ldsm_x4(uint32_t& r0, uint32_t& r1, uint32_t& r2, uint32_t& r3,
                                        uint32_t addr) {
    asm volatile("ldmatrix.sync.aligned.m8n8.x4.shared.b16 {%0, %1, %2, %3}, [%4];"
                 : "=r"(r0), "=r"(r1), "=r"(r2), "=r"(r3) : "r"(addr));
}

template <typename T> struct MmaOp;
template <> struct MmaOp<__nv_bfloat16> {
    static __device__ __forceinline__ void run(float* c, const uint32_t* a, uint32_t b0,
                                               uint32_t b1) {
        asm volatile(
            "mma.sync.aligned.m16n8k16.row.col.f32.bf16.bf16.f32 "
            "{%0, %1, %2, %3}, {%4, %5, %6, %7}, {%8, %9}, {%0, %1, %2, %3};"
            : "+f"(c[0]), "+f"(c[1]), "+f"(c[2]), "+f"(c[3])
            : "r"(a[0]), "r"(a[1]), "r"(a[2]), "r"(a[3]), "r"(b0), "r"(b1));
    }
};
template <> struct MmaOp<__half> {
    static __device__ __forceinline__ void run(float* c, const uint32_t* a, uint32_t b0,
                                               uint32_t b1) {
        asm volatile(
            "mma.sync.aligned.m16n8k16.row.col.f32.f16.f16.f32 "
            "{%0, %1, %2, %3}, {%4, %5, %6, %7}, {%8, %9}, {%0, %1, %2, %3};"
            : "+f"(c[0]), "+f"(c[1]), "+f"(c[2]), "+f"(c[3])
            : "r"(a[0]), "r"(a[1]), "r"(a[2]), "r"(a[3]), "r"(b0), "r"(b1));
    }
};

__device__ __forceinline__ void cp16(uint32_t dst, const void* src) {
    asm volatile("cp.async.cg.shared.global [%0], [%1], 16;" :: "r"(dst), "l"(src));
}
#define CP_COMMIT() asm volatile("cp.async.commit_group;" ::: "memory")
#define CP_WAIT1() asm volatile("cp.async.wait_group 1;" ::: "memory")

// packed f32x2
typedef unsigned long long ull;
__device__ __forceinline__ ull fma2(ull a, ull b, ull c) {
    ull d;
    asm("fma.rn.f32x2 %0, %1, %2, %3;" : "=l"(d) : "l"(a), "l"(b), "l"(c));
    return d;
}
__device__ __forceinline__ ull dup2(float a) {
    ull d;
    asm("mov.b64 %0, {%1, %1};" : "=l"(d) : "f"(a));
    return d;
}
__device__ __forceinline__ float lo2(ull a) {
    float x, y;
    asm("mov.b64 {%0, %1}, %2;" : "=f"(x), "=f"(y) : "l"(a));
    return x + y;
}
__device__ __forceinline__ float2 unp2(ull a) {
    float2 r;
    asm("mov.b64 {%0, %1}, %2;" : "=f"(r.x), "=f"(r.y) : "l"(a));
    return r;
}

// ================= conversion kernels =================
__global__ void split_all_kernel(const float* __restrict__ in,
                                 __nv_bfloat16* __restrict__ hi,
                                 __nv_bfloat16* __restrict__ lo,
                                 __half* __restrict__ h16,
                                 __half* __restrict__ l16) {
    int i = (blockIdx.x * 256 + threadIdx.x) * 4;
    float4 v = *(const float4*)&in[i];
    float f[4] = {v.x, v.y, v.z, v.w};
    union { __nv_bfloat16 b[4]; uint2 u; } H, L;
    union { __half b[4]; uint2 u; } H16, L16;
#pragma unroll
    for (int j = 0; j < 4; ++j) {
        __nv_bfloat16 h = __float2bfloat16(f[j]);
        H.b[j] = h;
        L.b[j] = __float2bfloat16(f[j] - __bfloat162float(h));
        __half p = __float2half_rn(f[j]);
        H16.b[j] = p;
        L16.b[j] = __float2half_rn(f[j] - __half2float(p));
    }
    *(uint2*)&hi[i] = H.u;
    *(uint2*)&lo[i] = L.u;
    *(uint2*)&h16[i] = H16.u;
    *(uint2*)&l16[i] = L16.u;
}

__global__ void transpose_split_kernel(const float* __restrict__ W,
                                       __nv_bfloat16* __restrict__ hi,
                                       __nv_bfloat16* __restrict__ lo,
                                       int rows, int cols) {
    __shared__ float t[32][33];
    int c0 = blockIdx.x * 32, r0 = blockIdx.y * 32;
    int tx = threadIdx.x, ty = threadIdx.y;
#pragma unroll
    for (int j = 0; j < 4; ++j) {
        int r = ty + j * 8;
        t[r][tx] = W[(size_t)(r0 + r) * cols + c0 + tx];
    }
    __syncthreads();
#pragma unroll
    for (int j = 0; j < 4; ++j) {
        int r = ty + j * 8;
        float v = t[tx][r];
        __nv_bfloat16 h = __float2bfloat16(v);
        size_t o = (size_t)(c0 + r) * rows + r0 + tx;
        hi[o] = h;
        lo[o] = __float2bfloat16(v - __bfloat162float(h));
    }
}

__global__ void transpose_f16_kernel(const float* __restrict__ W,
                                     __half* __restrict__ out, int rows, int cols) {
    __shared__ float t[32][33];
    int c0 = blockIdx.x * 32, r0 = blockIdx.y * 32;
    int tx = threadIdx.x, ty = threadIdx.y;
#pragma unroll
    for (int j = 0; j < 4; ++j) {
        int r = ty + j * 8;
        t[r][tx] = W[(size_t)(r0 + r) * cols + c0 + tx];
    }
    __syncthreads();
#pragma unroll
    for (int j = 0; j < 4; ++j) {
        int r = ty + j * 8;
        out[(size_t)(c0 + r) * rows + r0 + tx] = __float2half_rn(t[tx][r]);
    }
}

// ================= HMMA GEMM (R8 geometry — measured best: tensor 69%) =================
// CTA 128x64, 256 thr (8 warps 4x2, warp tile 32x32), K-chunk 64, cp.async 2-stage, 2 CTAs/SM.
template <typename T, bool SPLIT_B>
__global__ __launch_bounds__(256, 2)
void gemm_tc(const T* __restrict__ Ahi, const T* __restrict__ Alo,
             const T* __restrict__ Bhi, const T* __restrict__ Blo,
             float* __restrict__ C, int N, int K) {
    constexpr uint32_t B_OFF = 32768;
    constexpr uint32_t STG = B_OFF + (SPLIT_B ? 16384 : 8192);
    extern __shared__ char smem[];
    const uint32_t sb = smem_u32(smem);
    const int tid = threadIdx.x, lane = tid & 31, wid = tid >> 5;
    const int m0 = blockIdx.y * 128, n0 = blockIdx.x * 64;
    const int wm = (wid >> 1) * 32, wn = (wid & 1) * 32;

    const T* aptr[4];
    uint32_t asw[4];
#pragma unroll
    for (int i = 0; i < 4; ++i) {
        int idx = tid + (i << 8);
        int r = idx >> 3, c = idx & 7;
        aptr[i] = Ahi + (size_t)(m0 + r) * K + (c << 3);
        asw[i] = swz(r * 128 + c * 16);
    }
    const T* bptr[2];
    uint32_t bsw[2];
#pragma unroll
    for (int i = 0; i < 2; ++i) {
        int idx = tid + (i << 8);
        int r = idx >> 3, c = idx & 7;
        bptr[i] = Bhi + (size_t)(n0 + r) * K + (c << 3);
        bsw[i] = swz(r * 128 + c * 16);
    }
    const ptrdiff_t dA = Alo - Ahi;
    const ptrdiff_t dB = SPLIT_B ? (Blo - Bhi) : 0;

    float acc[2][4][4];
#pragma unroll
    for (int mt = 0; mt < 2; ++mt)
#pragma unroll
        for (int nt = 0; nt < 4; ++nt)
#pragma unroll
            for (int q = 0; q < 4; ++q) acc[mt][nt][q] = 0.f;

    const int NKT = K >> 6;
#pragma unroll
    for (int s = 0; s < 2; ++s) {
        const uint32_t st = sb + s * STG;
        const int ko = s * 64;
#pragma unroll
        for (int i = 0; i < 4; ++i) {
            cp16(st + asw[i], aptr[i] + ko);
            cp16(st + 16384 + asw[i], aptr[i] + dA + ko);
        }
#pragma unroll
        for (int i = 0; i < 2; ++i) {
            cp16(st + B_OFF + bsw[i], bptr[i] + ko);
            if (SPLIT_B) cp16(st + B_OFF + 8192 + bsw[i], bptr[i] + dB + ko);
        }
        CP_COMMIT();
    }

    const int row_off = ((lane >> 3) & 1) * 8 + (lane & 7);
    const int kxtra = (lane >> 4) * 16;
    const uint32_t a_lb = (uint32_t)((wm + row_off) * 128 + kxtra);
    const uint32_t b_lb = (uint32_t)((wn + row_off) * 128 + kxtra);

    for (int kt = 0; kt < NKT; ++kt) {
        CP_WAIT1();
        __syncthreads();
        const uint32_t st = sb + (uint32_t)(kt & 1) * STG;
#pragma unroll
        for (int ks = 0; ks < 4; ++ks) {
            uint32_t ah[2][4], al[2][4], bh[2][4];
#pragma unroll
            for (int mt = 0; mt < 2; ++mt) {
                uint32_t off = swz(a_lb + mt * 16 * 128 + ks * 32);
                ldsm_x4(ah[mt][0], ah[mt][1], ah[mt][2], ah[mt][3], st + off);
                ldsm_x4(al[mt][0], al[mt][1], al[mt][2], al[mt][3], st + 16384 + off);
            }
#pragma unroll
            for (int nt2 = 0; nt2 < 2; ++nt2)
                ldsm_x4(bh[nt2][0], bh[nt2][1], bh[nt2][2], bh[nt2][3],
                        st + B_OFF + swz(b_lb + nt2 * 16 * 128 + ks * 32));
            if (SPLIT_B) {
                uint32_t bl[2][4];
#pragma unroll
                for (int nt2 = 0; nt2 < 2; ++nt2)
                    ldsm_x4(bl[nt2][0], bl[nt2][1], bl[nt2][2], bl[nt2][3],
                            st + B_OFF + 8192 + swz(b_lb + nt2 * 16 * 128 + ks * 32));
#pragma unroll
                for (int mt = 0; mt < 2; ++mt)
#pragma unroll
                    for (int nt = 0; nt < 4; ++nt) {
                        MmaOp<T>::run(acc[mt][nt], ah[mt],
                                      bh[nt >> 1][nt & 1], bh[nt >> 1][2 + (nt & 1)]);
                        MmaOp<T>::run(acc[mt][nt], ah[mt],
                                      bl[nt >> 1][nt & 1], bl[nt >> 1][2 + (nt & 1)]);
                        MmaOp<T>::run(acc[mt][nt], al[mt],
                                      bh[nt >> 1][nt & 1], bh[nt >> 1][2 + (nt & 1)]);
                    }
            } else {
#pragma unroll
                for (int mt = 0; mt < 2; ++mt)
#pragma unroll
                    for (int nt = 0; nt < 4; ++nt) {
                        MmaOp<T>::run(acc[mt][nt], ah[mt],
                                      bh[nt >> 1][nt & 1], bh[nt >> 1][2 + (nt & 1)]);
                        MmaOp<T>::run(acc[mt][nt], al[mt],
                                      bh[nt >> 1][nt & 1], bh[nt >> 1][2 + (nt & 1)]);
                    }
            }
        }
        __syncthreads();
        if (kt + 2 < NKT) {
            const uint32_t st2 = sb + (uint32_t)(kt & 1) * STG;
            const int ko = (kt + 2) * 64;
#pragma unroll
            for (int i = 0; i < 4; ++i) {
                cp16(st2 + asw[i], aptr[i] + ko);
                cp16(st2 + 16384 + asw[i], aptr[i] + dA + ko);
            }
#pragma unroll
            for (int i = 0; i < 2; ++i) {
                cp16(st2 + B_OFF + bsw[i], bptr[i] + ko);
                if (SPLIT_B) cp16(st2 + B_OFF + 8192 + bsw[i], bptr[i] + dB + ko);
            }
        }
        CP_COMMIT();
    }

#pragma unroll
    for (int mt = 0; mt < 2; ++mt) {
        const int row = m0 + wm + mt * 16 + (lane >> 2);
#pragma unroll
        for (int nt = 0; nt < 4; ++nt) {
            const int col = n0 + wn + nt * 8 + (lane & 3) * 2;
            float* p0 = C + (size_t)row * N + col;
            *(float2*)p0 = make_float2(acc[mt][nt][0], acc[mt][nt][1]);
            *(float2*)(p0 + 8 * (size_t)N) = make_float2(acc[mt][nt][2], acc[mt][nt][3]);
        }
    }
}

// ---------------- RoPE ----------------
__global__ void rope_kernel(float* __restrict__ X, int nh) {
    const int s = blockIdx.x;
    const int d = threadIdx.x;
    const float e = (float)d * (1.0f / 64.0f);
    const float invf = 1.0f / powf(10000.0f, e);
    const float ang = (float)s * invf;
    float sn, cs;
    sincosf(ang, &sn, &cs);
    float* p = X + (size_t)s * nh * DH;
    for (int h = 0; h < nh; ++h) {
        const float x1 = p[d];
        const float x2 = p[d + 64];
        p[d] = x1 * cs - x2 * sn;
        p[d + 64] = x2 * cs + x1 * sn;
        p += DH;
    }
}

// ---------------- local windowed attention (512 threads, f32x2) ----------------
#define QP 132
#define KP 132
__global__ __launch_bounds__(512, 1)
void local_attn_kernel(const float* __restrict__ Q, const float* __restrict__ K,
                       const float* __restrict__ V, float* __restrict__ O) {
    extern __shared__ float sm[];
    float* sq = sm;
    float* sk = sq + 64 * QP;
    float* sv = sk + 128 * KP;
    float* sc = sv + 128 * 128;

    const int tid = threadIdx.x;
    const int h = blockIdx.y;
    const int n = blockIdx.x;
    const int kvh = h >> 2;
    const int q0 = n * 64;
    const int key0 = q0 - 64;

#pragma unroll
    for (int it = 0; it < 4; ++it) {
        int idx = tid + it * 512;
        int r = idx >> 5, c4 = idx & 31;
        float4 v4 = *(const float4*)&Q[(size_t)(q0 + r) * (NH * DH) + h * DH + c4 * 4];
        *(float4*)&sq[r * QP + c4 * 4] = v4;
    }
#pragma unroll
    for (int it = 0; it < 8; ++it) {
        int idx = tid + it * 512;
        int r = idx >> 5, c4 = idx & 31;
        int pos = key0 + r;
        float4 kv = make_float4(0.f, 0.f, 0.f, 0.f);
        float4 vv = make_float4(0.f, 0.f, 0.f, 0.f);
        if (pos >= 0) {
            kv = *(const float4*)&K[(size_t)pos * (NKV * DH) + kvh * DH + c4 * 4];
            vv = *(const float4*)&V[(size_t)pos * (NKV * DH) + kvh * DH + c4 * 4];
        }
        *(float4*)&sk[r * KP + c4 * 4] = kv;
        *(float4*)&sv[r * 128 + c4 * 4] = vv;
    }
    __syncthreads();

    // scores: 8 threads per query, 8 keys each (+1 extra for jo==0)
    {
        const int i = tid >> 3;
        const int jo = tid & 7;
        ull s2[8];
        ull s642 = 0;
#pragma unroll
        for (int m = 0; m < 8; ++m) s2[m] = 0;
        const float* qrow = sq + i * QP;
        for (int d0 = 0; d0 < 128; d0 += 8) {
            ull q2[4];
            q2[0] = *(const ull*)&qrow[d0];
            q2[1] = *(const ull*)&qrow[d0 + 2];
            q2[2] = *(const ull*)&qrow[d0 + 4];
            q2[3] = *(const ull*)&qrow[d0 + 6];
#pragma unroll
            for (int m = 0; m < 8; ++m) {
                const ull* kr = (const ull*)(sk + (i + jo + 8 * m) * KP + d0);
#pragma unroll
                for (int dd = 0; dd < 4; ++dd) s2[m] = fma2(q2[dd], kr[dd], s2[m]);
            }
            if (jo == 0) {
                const ull* kr = (const ull*)(sk + (i + 64) * KP + d0);
#pragma unroll
                for (int dd = 0; dd < 4; ++dd) s642 = fma2(q2[dd], kr[dd], s642);
            }
        }
#pragma unroll
        for (int m = 0; m < 8; ++m) sc[i * 66 + jo + 8 * m] = lo2(s2[m]) * ATT_SCALE;
        if (jo == 0) sc[i * 66 + 64] = lo2(s642) * ATT_SCALE;
    }
    __syncthreads();

    if (tid < 64) {
        float* row = sc + tid * 66;
        float mx = row[0];
        for (int j = 1; j < 65; ++j) mx = fmaxf(mx, row[j]);
        float sum = 0.f;
        for (int j = 0; j < 65; ++j) {
            float ex = expf(row[j] - mx);
            row[j] = ex;
            sum += ex;
        }
        float inv = 1.f / sum;
        for (int j = 0; j < 65; ++j) row[j] *= inv;
    }
    __syncthreads();

    // AV: 16 warps, 4 queries each
    {
        const int w = tid >> 5, lane = tid & 31;
        for (int iq = 0; iq < 4; ++iq) {
            const int i = w * 4 + iq;
            const float* wrow = sc + i * 66;
            ull o0 = 0, o1 = 0;
#pragma unroll 5
            for (int jj = 0; jj < 65; ++jj) {
                ull wt2 = dup2(wrow[jj]);
                const ull* v2 = (const ull*)(sv + (i + jj) * 128 + lane * 4);
                o0 = fma2(wt2, v2[0], o0);
                o1 = fma2(wt2, v2[1], o1);
            }
            float2 a = unp2(o0), b = unp2(o1);
            float4 res = make_float4(0.7f * a.x, 0.7f * a.y, 0.7f * b.x, 0.7f * b.y);
            *(float4*)&O[(size_t)(q0 + i) * (NH * DH) + h * DH + lane * 4] = res;
        }
    }
}

// ---------------- landmark attention (512 threads, f32x2; writes fp16 hi/lo) ----------------
__global__ __launch_bounds__(512, 1)
void lm_attn_kernel(const float* __restrict__ Q, const float* __restrict__ K,
                    const float* __restrict__ V, const float* __restrict__ OL,
                    __half* __restrict__ atHi, __half* __restrict__ atLo) {
    extern __shared__ float sm[];
    float* sq = sm;
    float* slk = sq + 64 * QP;
    float* slv = slk + 64 * QP;
    float* sc = slv + 64 * 128;

    const int tid = threadIdx.x;
    const int h = blockIdx.y;
    const int c = blockIdx.x;
    const int kvh = h >> 2;
    const int q0 = c * 64;
    const int nvis = c + 1;

#pragma unroll
    for (int it = 0; it < 4; ++it) {
        int idx = tid + it * 512;
        int r = idx >> 5, c4 = idx & 31;
        *(float4*)&sq[r * QP + c4 * 4] =
            *(const float4*)&Q[(size_t)(q0 + r) * (NH * DH) + h * DH + c4 * 4];
    }
#pragma unroll
    for (int it = 0; it < 4; ++it) {
        int idx = tid + it * 512;
        int r = idx >> 5, c4 = idx & 31;
        int pos = r * 64;
        *(float4*)&slk[r * QP + c4 * 4] =
            *(const float4*)&K[(size_t)pos * (NKV * DH) + kvh * DH + c4 * 4];
        *(float4*)&slv[r * 128 + c4 * 4] =
            *(const float4*)&V[(size_t)pos * (NKV * DH) + kvh * DH + c4 * 4];
    }
    __syncthreads();

    {
        const int i = tid >> 3;
        const int jo = tid & 7;
        ull s2[8];
#pragma unroll
        for (int m = 0; m < 8; ++m) s2[m] = 0;
        const float* qrow = sq + i * QP;
        for (int d0 = 0; d0 < 128; d0 += 8) {
            ull q2[4];
            q2[0] = *(const ull*)&qrow[d0];
            q2[1] = *(const ull*)&qrow[d0 + 2];
            q2[2] = *(const ull*)&qrow[d0 + 4];
            q2[3] = *(const ull*)&qrow[d0 + 6];
#pragma unroll
            for (int m = 0; m < 8; ++m) {
                const ull* kr = (const ull*)(slk + (jo + 8 * m) * QP + d0);
#pragma unroll
                for (int dd = 0; dd < 4; ++dd) s2[m] = fma2(q2[dd], kr[dd], s2[m]);
            }
        }
#pragma unroll
        for (int m = 0; m < 8; ++m) {
            int jj = jo + 8 * m;
            if (jj < nvis) sc[i * 66 + jj] = lo2(s2[m]) * ATT_SCALE;
        }
    }
    __syncthreads();

    if (tid < 64) {
        float* row = sc + tid * 66;
        float mx = row[0];
        for (int j = 1; j < nvis; ++j) mx = fmaxf(mx, row[j]);
        float sum = 0.f;
        for (int j = 0; j < nvis; ++j) {
            float ex = expf(row[j] - mx);
            row[j] = ex;
            sum += ex;
        }
        float inv = 1.f / sum;
        for (int j = 0; j < nvis; ++j) row[j] *= inv;
    }
    __syncthreads();

    {
        const int w = tid >> 5, lane = tid & 31;
        for (int iq = 0; iq < 4; ++iq) {
            const int i = w * 4 + iq;
            const float* wrow = sc + i * 66;
            ull o0 = 0, o1 = 0;
            for (int jj = 0; jj < nvis; ++jj) {
                ull wt2 = dup2(wrow[jj]);
                const ull* v2 = (const ull*)(slv + jj * 128 + lane * 4);
                o0 = fma2(wt2, v2[0], o0);
                o1 = fma2(wt2, v2[1], o1);
            }
            float2 a = unp2(o0), b = unp2(o1);
            size_t idx = (size_t)(q0 + i) * (NH * DH) + h * DH + lane * 4;
            float4 old = *(const float4*)&OL[idx];
            float s4[4] = {old.x + 0.3f * a.x, old.y + 0.3f * a.y,
                           old.z + 0.3f * b.x, old.w + 0.3f * b.y};
            union { __half b2[4]; uint2 u; } H, L;
#pragma unroll
            for (int q = 0; q < 4; ++q) {
                __half hb = __float2half_rn(s4[q]);
                H.b2[q] = hb;
                L.b2[q] = __float2half_rn(s4[q] - __half2float(hb));
            }
            *(uint2*)&atHi[idx] = H.u;
            *(uint2*)&atLo[idx] = L.u;
        }
    }
}

// ---------------- launch ----------------
extern "C" void kernel_launch(void* const* d_in, const int* in_sizes, int n_in,
                              void* d_out, int out_size) {
    const float* hs = (const float*)d_in[0];
    const float* wq = (const float*)d_in[1];
    const float* wk = (const float*)d_in[2];
    const float* wv = (const float*)d_in[3];
    const float* wo = (const float*)d_in[4];
    float* out = (float*)d_out;

    float *Q, *K, *V, *AT;
    __nv_bfloat16 *hsHi, *hsLo, *wqTHi, *wqTLo, *wkTHi, *wkTLo;
    __half *hs16h, *hs16l, *wvT16, *woT16, *at16h, *at16l;
    cudaGetSymbolAddress((void**)&Q, g_Q);
    cudaGetSymbolAddress((void**)&K, g_K);
    cudaGetSymbolAddress((void**)&V, g_V);
    cudaGetSymbolAddress((void**)&AT, g_attn);
    cudaGetSymbolAddress((void**)&hsHi, g_hsHi);
    cudaGetSymbolAddress((void**)&hsLo, g_hsLo);
    cudaGetSymbolAddress((void**)&hs16h, g_hs16h);
    cudaGetSymbolAddress((void**)&hs16l, g_hs16l);
    cudaGetSymbolAddress((void**)&wqTHi, g_wqTHi);
    cudaGetSymbolAddress((void**)&wqTLo, g_wqTLo);
    cudaGetSymbolAddress((void**)&wkTHi, g_wkTHi);
    cudaGetSymbolAddress((void**)&wkTLo, g_wkTLo);
    cudaGetSymbolAddress((void**)&wvT16, g_wvT16);
    cudaGetSymbolAddress((void**)&woT16, g_woT16);
    cudaGetSymbolAddress((void**)&at16h, g_at16h);
    cudaGetSymbolAddress((void**)&at16l, g_at16l);

    const int SMEM_LOCAL = (64 * QP + 128 * KP + 128 * 128 + 64 * 66) * 4;
    const int SMEM_LM = (64 * QP + 64 * QP + 64 * 128 + 64 * 66) * 4;
    const int SMEM_G3 = 2 * (32768 + 16384);  // 98304
    const int SMEM_G2 = 2 * (32768 + 8192);   // 81920
    cudaFuncSetAttribute(local_attn_kernel, cudaFuncAttributeMaxDynamicSharedMemorySize, SMEM_LOCAL);
    cudaFuncSetAttribute(lm_attn_kernel, cudaFuncAttributeMaxDynamicSharedMemorySize, SMEM_LM);
    cudaFuncSetAttribute(gemm_tc<__nv_bfloat16, true>,
                         cudaFuncAttributeMaxDynamicSharedMemorySize, SMEM_G3);
    cudaFuncSetAttribute(gemm_tc<__half, false>,
                         cudaFuncAttributeMaxDynamicSharedMemorySize, SMEM_G2);

    // 1-3: conversions feeding Q gemm
    split_all_kernel<<<(S_LEN * HID) / 1024, 256>>>(hs, hsHi, hsLo, hs16h, hs16l);
    transpose_split_kernel<<<dim3(HID / 32, HID / 32), dim3(32, 8)>>>(wq, wqTHi, wqTLo, HID, HID);
    transpose_f16_kernel<<<dim3((NKV * DH) / 32, HID / 32), dim3(32, 8)>>>(wv, wvT16, HID, NKV * DH);

    // 4: Q gemm (ncu capture slot)
    gemm_tc<__nv_bfloat16, true><<<dim3((NH * DH) / 64, S_LEN / 128), 256, SMEM_G3>>>(
        hsHi, hsLo, wqTHi, wqTLo, Q, NH * DH, HID);

    transpose_split_kernel<<<dim3((NKV * DH) / 32, HID / 32), dim3(32, 8)>>>(wk, wkTHi, wkTLo, HID, NKV * DH);
    gemm_tc<__nv_bfloat16, true><<<dim3((NKV * DH) / 64, S_LEN / 128), 256, SMEM_G3>>>(
        hsHi, hsLo, wkTHi, wkTLo, K, NKV * DH, HID);

    gemm_tc<__half, false><<<dim3((NKV * DH) / 64, S_LEN / 128), 256, SMEM_G2>>>(
        hs16h, hs16l, wvT16, (const __half*)nullptr, V, NKV * DH, HID);

    transpose_f16_kernel<<<dim3(HID / 32, HID / 32), dim3(32, 8)>>>(wo, woT16, HID, HID);

    rope_kernel<<<S_LEN, 64>>>(Q, NH);
    rope_kernel<<<S_LEN, 64>>>(K, NKV);

    local_attn_kernel<<<dim3(S_LEN / 64, NH), 512, SMEM_LOCAL>>>(Q, K, V, AT);
    lm_attn_kernel<<<dim3(S_LEN / 64, NH), 512, SMEM_LM>>>(Q, K, V, AT, at16h, at16l);

    gemm_tc<__half, false><<<dim3(HID / 64, S_LEN / 128), 256, SMEM_G2>>>(
        at16h, at16l, woT16, (const __half*)nullptr, out, HID, HID);
}

// round 11
// speedup vs baseline: 1.1676x; 1.0581x over previous
#include <cuda_runtime.h>
#include <cuda_bf16.h>
#include <cuda_fp16.h>
#include <math.h>
#include <stdint.h>

#define S_LEN 4096
#define HID 4096
#define NH 32
#define NKV 8
#define DH 128
#define ATT_SCALE 0.08838834764831845f  // 1/sqrt(128)

// ---------------- scratch ----------------
__device__ float g_Q[S_LEN * NH * DH];
__device__ float g_K[S_LEN * NKV * DH];
__device__ float g_V[S_LEN * NKV * DH];
__device__ __nv_bfloat16 g_hsHi[S_LEN * HID];
__device__ __nv_bfloat16 g_hsLo[S_LEN * HID];
__device__ __half g_hs16h[S_LEN * HID];
__device__ __half g_hs16l[S_LEN * HID];
__device__ __nv_bfloat16 g_wqkTHi[(HID + NKV * DH) * HID];  // wq rows 0..4095, wk rows 4096..5119
__device__ __nv_bfloat16 g_wqkTLo[(HID + NKV * DH) * HID];
__device__ __half g_wvT16[(NKV * DH) * HID];
__device__ __half g_woT16[HID * HID];
__device__ __half g_at16h[S_LEN * NH * DH];
__device__ __half g_at16l[S_LEN * NH * DH];

// ================= helpers =================
__device__ __forceinline__ uint32_t smem_u32(const void* p) {
    uint32_t a;
    asm("{ .reg .u64 t; cvta.to.shared.u64 t, %1; cvt.u32.u64 %0, t; }" : "=r"(a) : "l"(p));
    return a;
}
__device__ __forceinline__ uint32_t swz(uint32_t o) { return o ^ ((o >> 3) & 0x70); }

__device__ __forceinline__ void ldsm_x4(uint32_t& r0, uint32_t& r1, uint32_t& r2, uint32_t& r3,
                                        uint32_t addr) {
    asm volatile("ldmatrix.sync.aligned.m8n8.x4.shared.b16 {%0, %1, %2, %3}, [%4];"
                 : "=r"(r0), "=r"(r1), "=r"(r2), "=r"(r3) : "r"(addr));
}

template <typename T> struct MmaOp;
template <> struct MmaOp<__nv_bfloat16> {
    static __device__ __forceinline__ void run(float* c, const uint32_t* a, uint32_t b0,
                                               uint32_t b1) {
        asm volatile(
            "mma.sync.aligned.m16n8k16.row.col.f32.bf16.bf16.f32 "
            "{%0, %1, %2, %3}, {%4, %5, %6, %7}, {%8, %9}, {%0, %1, %2, %3};"
            : "+f"(c[0]), "+f"(c[1]), "+f"(c[2]), "+f"(c[3])
            : "r"(a[0]), "r"(a[1]), "r"(a[2]), "r"(a[3]), "r"(b0), "r"(b1));
    }
};
template <> struct MmaOp<__half> {
    static __device__ __forceinline__ void run(float* c, const uint32_t* a, uint32_t b0,
                                               uint32_t b1) {
        asm volatile(
            "mma.sync.aligned.m16n8k16.row.col.f32.f16.f16.f32 "
            "{%0, %1, %2, %3}, {%4, %5, %6, %7}, {%8, %9}, {%0, %1, %2, %3};"
            : "+f"(c[0]), "+f"(c[1]), "+f"(c[2]), "+f"(c[3])
            : "r"(a[0]), "r"(a[1]), "r"(a[2]), "r"(a[3]), "r"(b0), "r"(b1));
    }
};

__device__ __forceinline__ void cp16(uint32_t dst, const void* src) {
    asm volatile("cp.async.cg.shared.global [%0], [%1], 16;" :: "r"(dst), "l"(src));
}
#define CP_COMMIT() asm volatile("cp.async.commit_group;" ::: "memory")
#define CP_WAIT1() asm volatile("cp.async.wait_group 1;" ::: "memory")

// packed f32x2
typedef unsigned long long ull;
__device__ __forceinline__ ull fma2(ull a, ull b, ull c) {
    ull d;
    asm("fma.rn.f32x2 %0, %1, %2, %3;" : "=l"(d) : "l"(a), "l"(b), "l"(c));
    return d;
}
__device__ __forceinline__ ull dup2(float a) {
    ull d;
    asm("mov.b64 %0, {%1, %1};" : "=l"(d) : "f"(a));
    return d;
}
__device__ __forceinline__ float lo2(ull a) {
    float x, y;
    asm("mov.b64 {%0, %1}, %2;" : "=f"(x), "=f"(y) : "l"(a));
    return x + y;
}
__device__ __forceinline__ float2 unp2(ull a) {
    float2 r;
    asm("mov.b64 {%0, %1}, %2;" : "=f"(r.x), "=f"(r.y) : "l"(a));
    return r;
}

// ================= conversion kernels =================
__global__ void split_all_kernel(const float* __restrict__ in,
                                 __nv_bfloat16* __restrict__ hi,
                                 __nv_bfloat16* __restrict__ lo,
                                 __half* __restrict__ h16,
                                 __half* __restrict__ l16) {
    int i = (blockIdx.x * 256 + threadIdx.x) * 4;
    float4 v = *(const float4*)&in[i];
    float f[4] = {v.x, v.y, v.z, v.w};
    union { __nv_bfloat16 b[4]; uint2 u; } H, L;
    union { __half b[4]; uint2 u; } H16, L16;
#pragma unroll
    for (int j = 0; j < 4; ++j) {
        __nv_bfloat16 h = __float2bfloat16(f[j]);
        H.b[j] = h;
        L.b[j] = __float2bfloat16(f[j] - __bfloat162float(h));
        __half p = __float2half_rn(f[j]);
        H16.b[j] = p;
        L16.b[j] = __float2half_rn(f[j] - __half2float(p));
    }
    *(uint2*)&hi[i] = H.u;
    *(uint2*)&lo[i] = L.u;
    *(uint2*)&h16[i] = H16.u;
    *(uint2*)&l16[i] = L16.u;
}

__global__ void transpose_split_kernel(const float* __restrict__ W,
                                       __nv_bfloat16* __restrict__ hi,
                                       __nv_bfloat16* __restrict__ lo,
                                       int rows, int cols) {
    __shared__ float t[32][33];
    int c0 = blockIdx.x * 32, r0 = blockIdx.y * 32;
    int tx = threadIdx.x, ty = threadIdx.y;
#pragma unroll
    for (int j = 0; j < 4; ++j) {
        int r = ty + j * 8;
        t[r][tx] = W[(size_t)(r0 + r) * cols + c0 + tx];
    }
    __syncthreads();
#pragma unroll
    for (int j = 0; j < 4; ++j) {
        int r = ty + j * 8;
        float v = t[tx][r];
        __nv_bfloat16 h = __float2bfloat16(v);
        size_t o = (size_t)(c0 + r) * rows + r0 + tx;
        hi[o] = h;
        lo[o] = __float2bfloat16(v - __bfloat162float(h));
    }
}

__global__ void transpose_f16_kernel(const float* __restrict__ W,
                                     __half* __restrict__ out, int rows, int cols) {
    __shared__ float t[32][33];
    int c0 = blockIdx.x * 32, r0 = blockIdx.y * 32;
    int tx = threadIdx.x, ty = threadIdx.y;
#pragma unroll
    for (int j = 0; j < 4; ++j) {
        int r = ty + j * 8;
        t[r][tx] = W[(size_t)(r0 + r) * cols + c0 + tx];
    }
    __syncthreads();
#pragma unroll
    for (int j = 0; j < 4; ++j) {
        int r = ty + j * 8;
        out[(size_t)(c0 + r) * rows + r0 + tx] = __float2half_rn(t[tx][r]);
    }
}

// ================= HMMA GEMM (R8 geometry, dual-output epilogue) =================
// CTA 128x64, 256 thr (8 warps 4x2, warp tile 32x32), K-chunk 64, cp.async 2-stage, 2 CTAs/SM.
// Columns [0, N0) -> C0 (stride N0); columns [N0, N0+N1) -> C1 (stride N1).
template <typename T, bool SPLIT_B>
__global__ __launch_bounds__(256, 2)
void gemm_tc(const T* __restrict__ Ahi, const T* __restrict__ Alo,
             const T* __restrict__ Bhi, const T* __restrict__ Blo,
             float* __restrict__ C0, float* __restrict__ C1,
             int N0, int N1, int K) {
    constexpr uint32_t B_OFF = 32768;
    constexpr uint32_t STG = B_OFF + (SPLIT_B ? 16384 : 8192);
    extern __shared__ char smem[];
    const uint32_t sb = smem_u32(smem);
    const int tid = threadIdx.x, lane = tid & 31, wid = tid >> 5;
    const int m0 = blockIdx.y * 128, n0 = blockIdx.x * 64;
    const int wm = (wid >> 1) * 32, wn = (wid & 1) * 32;

    const T* aptr[4];
    uint32_t asw[4];
#pragma unroll
    for (int i = 0; i < 4; ++i) {
        int idx = tid + (i << 8);
        int r = idx >> 3, c = idx & 7;
        aptr[i] = Ahi + (size_t)(m0 + r) * K + (c << 3);
        asw[i] = swz(r * 128 + c * 16);
    }
    const T* bptr[2];
    uint32_t bsw[2];
#pragma unroll
    for (int i = 0; i < 2; ++i) {
        int idx = tid + (i << 8);
        int r = idx >> 3, c = idx & 7;
        bptr[i] = Bhi + (size_t)(n0 + r) * K + (c << 3);
        bsw[i] = swz(r * 128 + c * 16);
    }
    const ptrdiff_t dA = Alo - Ahi;
    const ptrdiff_t dB = SPLIT_B ? (Blo - Bhi) : 0;

    float acc[2][4][4];
#pragma unroll
    for (int mt = 0; mt < 2; ++mt)
#pragma unroll
        for (int nt = 0; nt < 4; ++nt)
#pragma unroll
            for (int q = 0; q < 4; ++q) acc[mt][nt][q] = 0.f;

    const int NKT = K >> 6;
#pragma unroll
    for (int s = 0; s < 2; ++s) {
        const uint32_t st = sb + s * STG;
        const int ko = s * 64;
#pragma unroll
        for (int i = 0; i < 4; ++i) {
            cp16(st + asw[i], aptr[i] + ko);
            cp16(st + 16384 + asw[i], aptr[i] + dA + ko);
        }
#pragma unroll
        for (int i = 0; i < 2; ++i) {
            cp16(st + B_OFF + bsw[i], bptr[i] + ko);
            if (SPLIT_B) cp16(st + B_OFF + 8192 + bsw[i], bptr[i] + dB + ko);
        }
        CP_COMMIT();
    }

    const int row_off = ((lane >> 3) & 1) * 8 + (lane & 7);
    const int kxtra = (lane >> 4) * 16;
    const uint32_t a_lb = (uint32_t)((wm + row_off) * 128 + kxtra);
    const uint32_t b_lb = (uint32_t)((wn + row_off) * 128 + kxtra);

    for (int kt = 0; kt < NKT; ++kt) {
        CP_WAIT1();
        __syncthreads();
        const uint32_t st = sb + (uint32_t)(kt & 1) * STG;
#pragma unroll
        for (int ks = 0; ks < 4; ++ks) {
            uint32_t ah[2][4], al[2][4], bh[2][4];
#pragma unroll
            for (int mt = 0; mt < 2; ++mt) {
                uint32_t off = swz(a_lb + mt * 16 * 128 + ks * 32);
                ldsm_x4(ah[mt][0], ah[mt][1], ah[mt][2], ah[mt][3], st + off);
                ldsm_x4(al[mt][0], al[mt][1], al[mt][2], al[mt][3], st + 16384 + off);
            }
#pragma unroll
            for (int nt2 = 0; nt2 < 2; ++nt2)
                ldsm_x4(bh[nt2][0], bh[nt2][1], bh[nt2][2], bh[nt2][3],
                        st + B_OFF + swz(b_lb + nt2 * 16 * 128 + ks * 32));
            if (SPLIT_B) {
                uint32_t bl[2][4];
#pragma unroll
                for (int nt2 = 0; nt2 < 2; ++nt2)
                    ldsm_x4(bl[nt2][0], bl[nt2][1], bl[nt2][2], bl[nt2][3],
                            st + B_OFF + 8192 + swz(b_lb + nt2 * 16 * 128 + ks * 32));
#pragma unroll
                for (int mt = 0; mt < 2; ++mt)
#pragma unroll
                    for (int nt = 0; nt < 4; ++nt) {
                        MmaOp<T>::run(acc[mt][nt], ah[mt],
                                      bh[nt >> 1][nt & 1], bh[nt >> 1][2 + (nt & 1)]);
                        MmaOp<T>::run(acc[mt][nt], ah[mt],
                                      bl[nt >> 1][nt & 1], bl[nt >> 1][2 + (nt & 1)]);
                        MmaOp<T>::run(acc[mt][nt], al[mt],
                                      bh[nt >> 1][nt & 1], bh[nt >> 1][2 + (nt & 1)]);
                    }
            } else {
#pragma unroll
                for (int mt = 0; mt < 2; ++mt)
#pragma unroll
                    for (int nt = 0; nt < 4; ++nt) {
                        MmaOp<T>::run(acc[mt][nt], ah[mt],
                                      bh[nt >> 1][nt & 1], bh[nt >> 1][2 + (nt & 1)]);
                        MmaOp<T>::run(acc[mt][nt], al[mt],
                                      bh[nt >> 1][nt & 1], bh[nt >> 1][2 + (nt & 1)]);
                    }
            }
        }
        __syncthreads();
        if (kt + 2 < NKT) {
            const uint32_t st2 = sb + (uint32_t)(kt & 1) * STG;
            const int ko = (kt + 2) * 64;
#pragma unroll
            for (int i = 0; i < 4; ++i) {
                cp16(st2 + asw[i], aptr[i] + ko);
                cp16(st2 + 16384 + asw[i], aptr[i] + dA + ko);
            }
#pragma unroll
            for (int i = 0; i < 2; ++i) {
                cp16(st2 + B_OFF + bsw[i], bptr[i] + ko);
                if (SPLIT_B) cp16(st2 + B_OFF + 8192 + bsw[i], bptr[i] + dB + ko);
            }
        }
        CP_COMMIT();
    }

    // dual-output epilogue
    float* Cc;
    int Nc, col0;
    if (n0 < N0) {
        Cc = C0; Nc = N0; col0 = n0;
    } else {
        Cc = C1; Nc = N1; col0 = n0 - N0;
    }
#pragma unroll
    for (int mt = 0; mt < 2; ++mt) {
        const int row = m0 + wm + mt * 16 + (lane >> 2);
#pragma unroll
        for (int nt = 0; nt < 4; ++nt) {
            const int col = col0 + wn + nt * 8 + (lane & 3) * 2;
            float* p0 = Cc + (size_t)row * Nc + col;
            *(float2*)p0 = make_float2(acc[mt][nt][0], acc[mt][nt][1]);
            *(float2*)(p0 + 8 * (size_t)Nc) = make_float2(acc[mt][nt][2], acc[mt][nt][3]);
        }
    }
}

// ---------------- RoPE ----------------
__global__ void rope_kernel(float* __restrict__ X, int nh) {
    const int s = blockIdx.x;
    const int d = threadIdx.x;
    const float e = (float)d * (1.0f / 64.0f);
    const float invf = 1.0f / powf(10000.0f, e);
    const float ang = (float)s * invf;
    float sn, cs;
    sincosf(ang, &sn, &cs);
    float* p = X + (size_t)s * nh * DH;
    for (int h = 0; h < nh; ++h) {
        const float x1 = p[d];
        const float x2 = p[d + 64];
        p[d] = x1 * cs - x2 * sn;
        p[d + 64] = x2 * cs + x1 * sn;
        p += DH;
    }
}

// ---------------- fused attention (local + landmark), 512 threads, f32x2 ----------------
// Phase 1: local windowed attention -> 0.7*out held in registers.
// Phase 2: landmark attention on reused smem -> out += 0.3*lm, write fp16 hi/lo.
#define QP 132
#define KP 132
__global__ __launch_bounds__(512, 1)
void fused_attn_kernel(const float* __restrict__ Q, const float* __restrict__ K,
                       const float* __restrict__ V,
                       __half* __restrict__ atHi, __half* __restrict__ atLo) {
    extern __shared__ float sm[];
    float* sq = sm;                 // 64 x 132 (lives through both phases)
    float* sk = sq + 64 * QP;       // 128 x 132 (phase2: landmark K 64 x 132)
    float* sv = sk + 128 * KP;      // 128 x 128 (phase2: landmark V 64 x 128)
    float* sc = sv + 128 * 128;     // 64 x 66

    const int tid = threadIdx.x;
    const int h = blockIdx.y;
    const int n = blockIdx.x;       // query block (= landmark chunk index)
    const int kvh = h >> 2;
    const int q0 = n * 64;
    const int key0 = q0 - 64;
    const int w = tid >> 5, lane = tid & 31;

    // ---- load Q (resident both phases) + local K/V window ----
#pragma unroll
    for (int it = 0; it < 4; ++it) {
        int idx = tid + it * 512;
        int r = idx >> 5, c4 = idx & 31;
        float4 v4 = *(const float4*)&Q[(size_t)(q0 + r) * (NH * DH) + h * DH + c4 * 4];
        *(float4*)&sq[r * QP + c4 * 4] = v4;
    }
#pragma unroll
    for (int it = 0; it < 8; ++it) {
        int idx = tid + it * 512;
        int r = idx >> 5, c4 = idx & 31;
        int pos = key0 + r;
        float4 kv = make_float4(0.f, 0.f, 0.f, 0.f);
        float4 vv = make_float4(0.f, 0.f, 0.f, 0.f);
        if (pos >= 0) {
            kv = *(const float4*)&K[(size_t)pos * (NKV * DH) + kvh * DH + c4 * 4];
            vv = *(const float4*)&V[(size_t)pos * (NKV * DH) + kvh * DH + c4 * 4];
        }
        *(float4*)&sk[r * KP + c4 * 4] = kv;
        *(float4*)&sv[r * 128 + c4 * 4] = vv;
    }
    __syncthreads();

    // ---- phase 1 scores ----
    {
        const int i = tid >> 3;
        const int jo = tid & 7;
        ull s2[8];
        ull s642 = 0;
#pragma unroll
        for (int m = 0; m < 8; ++m) s2[m] = 0;
        const float* qrow = sq + i * QP;
        for (int d0 = 0; d0 < 128; d0 += 8) {
            ull q2[4];
            q2[0] = *(const ull*)&qrow[d0];
            q2[1] = *(const ull*)&qrow[d0 + 2];
            q2[2] = *(const ull*)&qrow[d0 + 4];
            q2[3] = *(const ull*)&qrow[d0 + 6];
#pragma unroll
            for (int m = 0; m < 8; ++m) {
                const ull* kr = (const ull*)(sk + (i + jo + 8 * m) * KP + d0);
#pragma unroll
                for (int dd = 0; dd < 4; ++dd) s2[m] = fma2(q2[dd], kr[dd], s2[m]);
            }
            if (jo == 0) {
                const ull* kr = (const ull*)(sk + (i + 64) * KP + d0);
#pragma unroll
                for (int dd = 0; dd < 4; ++dd) s642 = fma2(q2[dd], kr[dd], s642);
            }
        }
#pragma unroll
        for (int m = 0; m < 8; ++m) sc[i * 66 + jo + 8 * m] = lo2(s2[m]) * ATT_SCALE;
        if (jo == 0) sc[i * 66 + 64] = lo2(s642) * ATT_SCALE;
    }
    __syncthreads();

    // ---- phase 1 softmax (65 slots) ----
    if (tid < 64) {
        float* row = sc + tid * 66;
        float mx = row[0];
        for (int j = 1; j < 65; ++j) mx = fmaxf(mx, row[j]);
        float sum = 0.f;
        for (int j = 0; j < 65; ++j) {
            float ex = expf(row[j] - mx);
            row[j] = ex;
            sum += ex;
        }
        float inv = 1.f / sum;
        for (int j = 0; j < 65; ++j) row[j] *= inv;
    }
    __syncthreads();

    // ---- phase 1 AV -> registers (0.7x), 16 warps x 4 queries ----
    ull lo_[4][2];
#pragma unroll
    for (int iq = 0; iq < 4; ++iq) {
        const int i = w * 4 + iq;
        const float* wrow = sc + i * 66;
        ull o0 = 0, o1 = 0;
#pragma unroll 5
        for (int jj = 0; jj < 65; ++jj) {
            ull wt2 = dup2(wrow[jj]);
            const ull* v2 = (const ull*)(sv + (i + jj) * 128 + lane * 4);
            o0 = fma2(wt2, v2[0], o0);
            o1 = fma2(wt2, v2[1], o1);
        }
        lo_[iq][0] = o0;
        lo_[iq][1] = o1;
    }
    __syncthreads();  // all phase-1 reads of sk/sv/sc done

    // ---- phase 2: load landmark K/V (64 landmarks at stride 64) ----
#pragma unroll
    for (int it = 0; it < 4; ++it) {
        int idx = tid + it * 512;
        int r = idx >> 5, c4 = idx & 31;
        int pos = r * 64;
        *(float4*)&sk[r * KP + c4 * 4] =
            *(const float4*)&K[(size_t)pos * (NKV * DH) + kvh * DH + c4 * 4];
        *(float4*)&sv[r * 128 + c4 * 4] =
            *(const float4*)&V[(size_t)pos * (NKV * DH) + kvh * DH + c4 * 4];
    }
    __syncthreads();

    const int nvis = n + 1;
    // ---- phase 2 scores ----
    {
        const int i = tid >> 3;
        const int jo = tid & 7;
        ull s2[8];
#pragma unroll
        for (int m = 0; m < 8; ++m) s2[m] = 0;
        const float* qrow = sq + i * QP;
        for (int d0 = 0; d0 < 128; d0 += 8) {
            ull q2[4];
            q2[0] = *(const ull*)&qrow[d0];
            q2[1] = *(const ull*)&qrow[d0 + 2];
            q2[2] = *(const ull*)&qrow[d0 + 4];
            q2[3] = *(const ull*)&qrow[d0 + 6];
#pragma unroll
            for (int m = 0; m < 8; ++m) {
                const ull* kr = (const ull*)(sk + (jo + 8 * m) * KP + d0);
#pragma unroll
                for (int dd = 0; dd < 4; ++dd) s2[m] = fma2(q2[dd], kr[dd], s2[m]);
            }
        }
#pragma unroll
        for (int m = 0; m < 8; ++m) {
            int jj = jo + 8 * m;
            if (jj < nvis) sc[i * 66 + jj] = lo2(s2[m]) * ATT_SCALE;
        }
    }
    __syncthreads();

    // ---- phase 2 softmax (nvis slots) ----
    if (tid < 64) {
        float* row = sc + tid * 66;
        float mx = row[0];
        for (int j = 1; j < nvis; ++j) mx = fmaxf(mx, row[j]);
        float sum = 0.f;
        for (int j = 0; j < nvis; ++j) {
            float ex = expf(row[j] - mx);
            row[j] = ex;
            sum += ex;
        }
        float inv = 1.f / sum;
        for (int j = 0; j < nvis; ++j) row[j] *= inv;
    }
    __syncthreads();

    // ---- phase 2 AV + combine + store fp16 hi/lo ----
#pragma unroll
    for (int iq = 0; iq < 4; ++iq) {
        const int i = w * 4 + iq;
        const float* wrow = sc + i * 66;
        ull o0 = 0, o1 = 0;
        for (int jj = 0; jj < nvis; ++jj) {
            ull wt2 = dup2(wrow[jj]);
            const ull* v2 = (const ull*)(sv + jj * 128 + lane * 4);
            o0 = fma2(wt2, v2[0], o0);
            o1 = fma2(wt2, v2[1], o1);
        }
        float2 ga = unp2(o0), gb = unp2(o1);
        float2 la = unp2(lo_[iq][0]), lb = unp2(lo_[iq][1]);
        float s4[4] = {0.7f * la.x + 0.3f * ga.x, 0.7f * la.y + 0.3f * ga.y,
                       0.7f * lb.x + 0.3f * gb.x, 0.7f * lb.y + 0.3f * gb.y};
        size_t idx = (size_t)(q0 + i) * (NH * DH) + h * DH + lane * 4;
        union { __half b2[4]; uint2 u; } H, L;
#pragma unroll
        for (int q = 0; q < 4; ++q) {
            __half hb = __float2half_rn(s4[q]);
            H.b2[q] = hb;
            L.b2[q] = __float2half_rn(s4[q] - __half2float(hb));
        }
        *(uint2*)&atHi[idx] = H.u;
        *(uint2*)&atLo[idx] = L.u;
    }
}

// ---------------- launch ----------------
extern "C" void kernel_launch(void* const* d_in, const int* in_sizes, int n_in,
                              void* d_out, int out_size) {
    const float* hs = (const float*)d_in[0];
    const float* wq = (const float*)d_in[1];
    const float* wk = (const float*)d_in[2];
    const float* wv = (const float*)d_in[3];
    const float* wo = (const float*)d_in[4];
    float* out = (float*)d_out;

    float *Q, *K, *V;
    __nv_bfloat16 *hsHi, *hsLo, *wqkTHi, *wqkTLo;
    __half *hs16h, *hs16l, *wvT16, *woT16, *at16h, *at16l;
    cudaGetSymbolAddress((void**)&Q, g_Q);
    cudaGetSymbolAddress((void**)&K, g_K);
    cudaGetSymbolAddress((void**)&V, g_V);
    cudaGetSymbolAddress((void**)&hsHi, g_hsHi);
    cudaGetSymbolAddress((void**)&hsLo, g_hsLo);
    cudaGetSymbolAddress((void**)&hs16h, g_hs16h);
    cudaGetSymbolAddress((void**)&hs16l, g_hs16l);
    cudaGetSymbolAddress((void**)&wqkTHi, g_wqkTHi);
    cudaGetSymbolAddress((void**)&wqkTLo, g_wqkTLo);
    cudaGetSymbolAddress((void**)&wvT16, g_wvT16);
    cudaGetSymbolAddress((void**)&woT16, g_woT16);
    cudaGetSymbolAddress((void**)&at16h, g_at16h);
    cudaGetSymbolAddress((void**)&at16l, g_at16l);

    const int SMEM_ATT = (64 * QP + 128 * KP + 128 * 128 + 64 * 66) * 4;
    const int SMEM_G3 = 2 * (32768 + 16384);  // 98304
    const int SMEM_G2 = 2 * (32768 + 8192);   // 81920
    cudaFuncSetAttribute(fused_attn_kernel, cudaFuncAttributeMaxDynamicSharedMemorySize, SMEM_ATT);
    cudaFuncSetAttribute(gemm_tc<__nv_bfloat16, true>,
                         cudaFuncAttributeMaxDynamicSharedMemorySize, SMEM_G3);
    cudaFuncSetAttribute(gemm_tc<__half, false>,
                         cudaFuncAttributeMaxDynamicSharedMemorySize, SMEM_G2);

    // 1-3: conversions feeding QK gemm
    split_all_kernel<<<(S_LEN * HID) / 1024, 256>>>(hs, hsHi, hsLo, hs16h, hs16l);
    transpose_split_kernel<<<dim3(HID / 32, HID / 32), dim3(32, 8)>>>(
        wq, wqkTHi, wqkTLo, HID, HID);
    transpose_split_kernel<<<dim3((NKV * DH) / 32, HID / 32), dim3(32, 8)>>>(
        wk, wqkTHi + (size_t)HID * HID, wqkTLo + (size_t)HID * HID, HID, NKV * DH);

    // 4: fused Q+K gemm (ncu capture slot), N = 4096 + 1024
    gemm_tc<__nv_bfloat16, true><<<dim3((HID + NKV * DH) / 64, S_LEN / 128), 256, SMEM_G3>>>(
        hsHi, hsLo, wqkTHi, wqkTLo, Q, K, NH * DH, NKV * DH, HID);

    transpose_f16_kernel<<<dim3((NKV * DH) / 32, HID / 32), dim3(32, 8)>>>(wv, wvT16, HID, NKV * DH);
    gemm_tc<__half, false><<<dim3((NKV * DH) / 64, S_LEN / 128), 256, SMEM_G2>>>(
        hs16h, hs16l, wvT16, (const __half*)nullptr, V, V, NKV * DH, 0, HID);

    transpose_f16_kernel<<<dim3(HID / 32, HID / 32), dim3(32, 8)>>>(wo, woT16, HID, HID);

    rope_kernel<<<S_LEN, 64>>>(Q, NH);
    rope_kernel<<<S_LEN, 64>>>(K, NKV);

    // fused local+landmark attention, writes fp16 hi/lo directly
    fused_attn_kernel<<<dim3(S_LEN / 64, NH), 512, SMEM_ATT>>>(Q, K, V, at16h, at16l);

    // O projection: fp16 2-pass
    gemm_tc<__half, false><<<dim3(HID / 64, S_LEN / 128), 256, SMEM_G2>>>(
        at16h, at16l, woT16, (const __half*)nullptr, out, out, HID, 0, HID);
}